// round 8
// baseline (speedup 1.0000x reference)
#include <cuda_runtime.h>
#include <math.h>
#include <stdint.h>

// ---------------- problem constants ----------------
#define kNQ 10000
#define kNS 500
#define kQN 4
#define kSN 10
#define kB  32
#define kS  200
#define kD  128
#define kT  199   // S-1

// ---------------- scratch layout (floats) ----------------
__host__ __device__ constexpr size_t O_TA0 = 0;                        // also reused as TC0
__host__ __device__ constexpr size_t O_TA1 = O_TA0 + (size_t)kNQ*kD;
__host__ __device__ constexpr size_t O_TA2 = O_TA1 + (size_t)kNS*kD;
__host__ __device__ constexpr size_t O_TB0 = O_TA2 + (size_t)kNQ*kD;
__host__ __device__ constexpr size_t O_TB1 = O_TB0 + (size_t)kNQ*kD;
__host__ __device__ constexpr size_t O_A   = O_TB1 + (size_t)kNS*kD;
__host__ __device__ constexpr size_t O_H   = O_A   + (size_t)kNQ*kD;
__host__ __device__ constexpr size_t O_AS  = O_H   + (size_t)kB*kS*kD;
__host__ __device__ constexpr size_t O_V   = O_AS  + (size_t)kB*kT;   // qv[128], kv[128], c_q, c_k
__host__ __device__ constexpr size_t O_RG  = O_V   + 258;             // r_gates 2x512
__host__ __device__ constexpr size_t G_TOTAL = O_RG + 1024;

__device__ float g_buf[G_TOTAL];

// ---------------- fast math ----------------
__device__ __forceinline__ float fast_tanh(float x) {
    float y;
    asm("tanh.approx.f32 %0, %1;" : "=f"(y) : "f"(x));
    return y;
}
__device__ __forceinline__ float fast_sigmoid(float x) {
    return 0.5f * fast_tanh(0.5f * x) + 0.5f;
}

// ---------------- task structs ----------------
struct HopTask {
    const float* base;
    const int*   nbrs;
    const float* tbl;
    const float* W;      // 128x128, row stride 128, read via L1 (not staged)
    const float* bias;
    float*       out;
    int knbr; float invk;
    int R; int blk0;
};
struct PrepArgs {
    const float *qW, *qb, *kW, *kb, *wW, *embr, *Wih, *bih, *bhh;
    int enable;
};
struct HopParams { HopTask t[3]; int nt; PrepArgs prep; };

// ---------------- hop kernel: 256 thr, 64 rows, 4x8 tile, W via L1 ----------------
__global__ __launch_bounds__(256, 4) void hop_kernel(const HopParams p)
{
    __shared__ float sIn[64*132];
    const int tid = threadIdx.x;

    // prep block (independent side-work; consumers run kernels later)
    if (p.prep.enable && blockIdx.x == (int)gridDim.x - 1) {
        const PrepArgs& A = p.prep;
        float* vec = g_buf + O_V;
        float* rg  = g_buf + O_RG;
        if (tid < kD) {
            float sq = 0.f, sk = 0.f;
            #pragma unroll 4
            for (int j = 0; j < kD; j++) {
                sq += A.qW[tid*kD + j] * A.wW[j];
                sk += A.kW[tid*kD + j] * A.wW[kD + j];
            }
            vec[tid]      = sq;
            vec[kD + tid] = sk;
        }
        if (tid == 128) {
            float s = 0.f;
            for (int j = 0; j < kD; j++) s += A.qb[j] * A.wW[j];
            vec[256] = s;
        }
        if (tid == 129) {
            float s = 0.f;
            for (int j = 0; j < kD; j++) s += A.kb[j] * A.wW[kD + j];
            vec[257] = s;
        }
        for (int c = tid; c < 512; c += 256) {
            for (int r = 0; r < 2; r++) {
                float s = A.bih[c] + A.bhh[c];
                #pragma unroll 4
                for (int k = 0; k < kD; k++)
                    s += A.embr[r*kD + k] * A.Wih[(size_t)(kD + k)*512 + c];
                rg[r*512 + c] = s;
            }
        }
        return;
    }

    int ti = 0;
    #pragma unroll
    for (int i = 1; i < 3; i++)
        if (i < p.nt && (int)blockIdx.x >= p.t[i].blk0) ti = i;
    const HopTask& T = p.t[ti];
    const int row0 = (blockIdx.x - T.blk0) * 64;

    // gather 64 rows (4 thr/row, 32 dims = 8 float4 each)
    {
        int lr = tid >> 2, part = tid & 3;
        int gr = row0 + lr;
        float4 v[8];
        if (gr < T.R) {
            const float4* bp = (const float4*)(T.base + (size_t)gr*kD) + part*8;
            #pragma unroll
            for (int d = 0; d < 8; d++) v[d] = __ldg(&bp[d]);
            if (T.knbr > 0) {
                float4 s[8];
                #pragma unroll
                for (int d = 0; d < 8; d++) s[d] = make_float4(0.f,0.f,0.f,0.f);
                for (int j = 0; j < T.knbr; j++) {
                    int nb = __ldg(&T.nbrs[(size_t)gr*T.knbr + j]);
                    const float4* tp = (const float4*)(T.tbl + (size_t)nb*kD) + part*8;
                    #pragma unroll
                    for (int d = 0; d < 8; d++) {
                        float4 x = __ldg(&tp[d]);
                        s[d].x += x.x; s[d].y += x.y; s[d].z += x.z; s[d].w += x.w;
                    }
                }
                #pragma unroll
                for (int d = 0; d < 8; d++) {
                    v[d].x += s[d].x * T.invk; v[d].y += s[d].y * T.invk;
                    v[d].z += s[d].z * T.invk; v[d].w += s[d].w * T.invk;
                }
            }
        } else {
            #pragma unroll
            for (int d = 0; d < 8; d++) v[d] = make_float4(0.f,0.f,0.f,0.f);
        }
        #pragma unroll
        for (int d = 0; d < 8; d++)
            *(float4*)(sIn + lr*132 + part*32 + d*4) = v[d];
    }
    __syncthreads();

    // 64x128 GEMM: thread tile 4 rows x 8 cols; B streamed via L1
    const int r0 = (tid >> 4) * 4;
    const int c0 = (tid & 15) * 8;
    float acc[4][8];
    #pragma unroll
    for (int i = 0; i < 4; i++)
        #pragma unroll
        for (int j = 0; j < 8; j++) acc[i][j] = 0.f;

    const float* Wc = T.W + c0;
    #pragma unroll 4
    for (int k = 0; k < kD; k++) {
        float a0 = sIn[(r0+0)*132 + k];
        float a1 = sIn[(r0+1)*132 + k];
        float a2 = sIn[(r0+2)*132 + k];
        float a3 = sIn[(r0+3)*132 + k];
        float4 b0 = __ldg((const float4*)(Wc + (size_t)k*kD));
        float4 b1 = __ldg((const float4*)(Wc + (size_t)k*kD) + 1);
        float bb[8] = {b0.x,b0.y,b0.z,b0.w,b1.x,b1.y,b1.z,b1.w};
        #pragma unroll
        for (int j = 0; j < 8; j++) {
            acc[0][j] += a0*bb[j];
            acc[1][j] += a1*bb[j];
            acc[2][j] += a2*bb[j];
            acc[3][j] += a3*bb[j];
        }
    }

    float bsv[8];
    #pragma unroll
    for (int j = 0; j < 8; j++) bsv[j] = __ldg(&T.bias[c0 + j]);

    #pragma unroll
    for (int i = 0; i < 4; i++) {
        int gr = row0 + r0 + i;
        if (gr >= T.R) continue;
        float4 o0, o1;
        o0.x = fast_tanh(acc[i][0] + bsv[0]); o0.y = fast_tanh(acc[i][1] + bsv[1]);
        o0.z = fast_tanh(acc[i][2] + bsv[2]); o0.w = fast_tanh(acc[i][3] + bsv[3]);
        o1.x = fast_tanh(acc[i][4] + bsv[4]); o1.y = fast_tanh(acc[i][5] + bsv[5]);
        o1.z = fast_tanh(acc[i][6] + bsv[6]); o1.w = fast_tanh(acc[i][7] + bsv[7]);
        *(float4*)(T.out + (size_t)gr*kD + c0)     = o0;
        *(float4*)(T.out + (size_t)gr*kD + c0 + 4) = o1;
    }
}

// ---------------- rowchain: 256 thr, 32 rows; ft then wide gates; W via L1 ----------------
__global__ __launch_bounds__(256, 3) void rowchain_kernel(
    const int* __restrict__ question, const int* __restrict__ response,
    const float* __restrict__ ft_W, const float* __restrict__ ft_b,
    const float* __restrict__ W_ih)
{
    __shared__ float sIn[32*132];
    __shared__ float sqv[kD];

    const float* A   = g_buf + O_A;
    const float* vec = g_buf + O_V;
    const float* RG  = g_buf + O_RG;
    float* H  = g_buf + O_H;
    float* AS = g_buf + O_AS;

    const int tid = threadIdx.x;
    const int row0 = blockIdx.x * 32;
    if (tid < kD) sqv[tid] = vec[tid];

    // gather A[question[row]] (8 threads/row, 16 dims = 4 float4)
    {
        int lr = tid >> 3, part = tid & 7;
        int grow = row0 + lr;
        int q = __ldg(&question[grow]);
        const float4* ap = (const float4*)(A + (size_t)q*kD) + part*4;
        #pragma unroll
        for (int d = 0; d < 4; d++)
            *(float4*)(sIn + lr*132 + part*16 + d*4) = __ldg(&ap[d]);
    }
    __syncthreads();

    const int r0 = (tid >> 4) * 2;     // 0..30
    const int c0 = (tid & 15) * 8;     // 0..120

    // stage 1: QT = relu(in @ ft_W + ft_b)
    float acc[2][8];
    #pragma unroll
    for (int i = 0; i < 2; i++)
        #pragma unroll
        for (int j = 0; j < 8; j++) acc[i][j] = 0.f;
    {
        const float* Wc = ft_W + c0;
        #pragma unroll 4
        for (int k = 0; k < kD; k++) {
            float a0 = sIn[(r0+0)*132 + k];
            float a1 = sIn[(r0+1)*132 + k];
            float4 b0 = __ldg((const float4*)(Wc + (size_t)k*kD));
            float4 b1 = __ldg((const float4*)(Wc + (size_t)k*kD) + 1);
            float bb[8] = {b0.x,b0.y,b0.z,b0.w,b1.x,b1.y,b1.z,b1.w};
            #pragma unroll
            for (int j = 0; j < 8; j++) {
                acc[0][j] += a0*bb[j];
                acc[1][j] += a1*bb[j];
            }
        }
    }
    float fb[8];
    #pragma unroll
    for (int j = 0; j < 8; j++) fb[j] = __ldg(&ft_b[c0 + j]);
    __syncthreads();                   // all reads of sIn done
    #pragma unroll
    for (int i = 0; i < 2; i++)
        #pragma unroll
        for (int j = 0; j < 8; j++)
            sIn[(r0+i)*132 + c0 + j] = fmaxf(acc[i][j] + fb[j], 0.f);
    __syncthreads();

    // stage 2: all three live gates in one pass; W_ih cols i=c0, g=256+c0, o=384+c0
    float ai[2][8], ag[2][8], ao[2][8];
    #pragma unroll
    for (int i = 0; i < 2; i++)
        #pragma unroll
        for (int j = 0; j < 8; j++) { ai[i][j]=0.f; ag[i][j]=0.f; ao[i][j]=0.f; }

    {
        const float* Wi = W_ih + c0;
        const float* Wg = W_ih + 256 + c0;
        const float* Wo = W_ih + 384 + c0;
        #pragma unroll 2
        for (int k = 0; k < kD; k++) {
            float a0 = sIn[(r0+0)*132 + k];
            float a1 = sIn[(r0+1)*132 + k];
            size_t ko = (size_t)k * 512;
            float4 i0 = __ldg((const float4*)(Wi + ko));
            float4 i1 = __ldg((const float4*)(Wi + ko) + 1);
            float4 g0 = __ldg((const float4*)(Wg + ko));
            float4 g1 = __ldg((const float4*)(Wg + ko) + 1);
            float4 o0 = __ldg((const float4*)(Wo + ko));
            float4 o1 = __ldg((const float4*)(Wo + ko) + 1);
            float ib[8] = {i0.x,i0.y,i0.z,i0.w,i1.x,i1.y,i1.z,i1.w};
            float gb[8] = {g0.x,g0.y,g0.z,g0.w,g1.x,g1.y,g1.z,g1.w};
            float ob[8] = {o0.x,o0.y,o0.z,o0.w,o1.x,o1.y,o1.z,o1.w};
            #pragma unroll
            for (int j = 0; j < 8; j++) {
                ai[0][j] += a0*ib[j]; ai[1][j] += a1*ib[j];
                ag[0][j] += a0*gb[j]; ag[1][j] += a1*gb[j];
                ao[0][j] += a0*ob[j]; ao[1][j] += a1*ob[j];
            }
        }
    }

    // epilogue: gates -> h in registers, write H, partial a_state
    const float cq = vec[256];
    #pragma unroll
    for (int i = 0; i < 2; i++) {
        int grow = row0 + r0 + i;
        int rr = __ldg(&response[grow]);
        const float* rgi = RG + rr*512 + 0   + c0;
        const float* rgg = RG + rr*512 + 256 + c0;
        const float* rgo = RG + rr*512 + 384 + c0;
        float hv[8];
        float p = 0.f;
        #pragma unroll
        for (int j = 0; j < 8; j++) {
            float iv = fast_sigmoid(ai[i][j] + rgi[j]);
            float gv = fast_tanh   (ag[i][j] + rgg[j]);
            float ov = fast_sigmoid(ao[i][j] + rgo[j]);
            hv[j] = ov * fast_tanh(iv * gv);
            p += hv[j] * sqv[c0 + j];
        }
        *(float4*)(H + (size_t)grow*kD + c0)     = make_float4(hv[0],hv[1],hv[2],hv[3]);
        *(float4*)(H + (size_t)grow*kD + c0 + 4) = make_float4(hv[4],hv[5],hv[6],hv[7]);
        // reduce over the 16 threads sharing this row
        p += __shfl_down_sync(0xffffffffu, p, 8, 16);
        p += __shfl_down_sync(0xffffffffu, p, 4, 16);
        p += __shfl_down_sync(0xffffffffu, p, 2, 16);
        p += __shfl_down_sync(0xffffffffu, p, 1, 16);
        if ((tid & 15) == 0) {
            int b = grow / kS, s = grow % kS;
            if (s < kT) AS[b*kT + s] = p + cq;
        }
    }
}

// ---------------- pred: 8 warps/block share b (h[b] L1-resident), 1 warp per t ----------------
__global__ __launch_bounds__(256, 4) void pred_kernel(
    const int* __restrict__ question,
    const int* __restrict__ qs_skills,
    const float* __restrict__ emb_q,
    const float* __restrict__ emb_s,
    float* __restrict__ out)
{
    __shared__ __align__(16) float sqs[8][5][kD];

    const float* vec = g_buf + O_V;
    const int b = blockIdx.y;
    const int w = threadIdx.x >> 5;
    const int lane = threadIdx.x & 31;
    const int t = 198 - ((int)blockIdx.x * 8 + w);   // big t first
    if (t < 0) return;

    const float* asb = g_buf + O_AS + b*kT;
    const float* hb  = g_buf + O_H  + (size_t)b*kS*kD;

    int q = __ldg(&question[b*kS + t + 1]);
    ((float4*)sqs[w][0])[lane] = __ldg((const float4*)(emb_q + (size_t)q*kD) + lane);
    #pragma unroll
    for (int m = 1; m < 5; m++) {
        int si = __ldg(&qs_skills[q*4 + m - 1]);
        ((float4*)sqs[w][m])[lane] = __ldg((const float4*)(emb_s + (size_t)si*kD) + lane);
    }
    __syncwarp();

    // a_qs[m] = dot(sqs[m], kv); softmax over m (c_k cancels)
    float4 kv4 = *((const float4*)(vec + kD) + lane);
    float r[5];
    #pragma unroll
    for (int m = 0; m < 5; m++) {
        float4 s4 = ((float4*)sqs[w][m])[lane];
        float p = s4.x*kv4.x + s4.y*kv4.y + s4.z*kv4.z + s4.w*kv4.w;
        #pragma unroll
        for (int o = 16; o; o >>= 1) p += __shfl_xor_sync(0xffffffffu, p, o);
        r[m] = p;
    }
    {
        float mx = r[0];
        #pragma unroll
        for (int m = 1; m < 5; m++) mx = fmaxf(mx, r[m]);
        float se = 0.f;
        #pragma unroll
        for (int m = 0; m < 5; m++) { r[m] = __expf(r[m] - mx); se += r[m]; }
        float inv = __frcp_rn(se);
        #pragma unroll
        for (int m = 0; m < 5; m++) r[m] *= inv;
    }

    // max of a_state over n<=t
    float M1 = -1e30f;
    for (int n = lane; n <= t; n += 32) M1 = fmaxf(M1, asb[n]);
    #pragma unroll
    for (int o = 16; o; o >>= 1) M1 = fmaxf(M1, __shfl_xor_sync(0xffffffffu, M1, o));

    float sum_v = 0.f, sum_e = 0.f;
    for (int n = lane; n <= t; n += 32) {
        float e = __expf(asb[n] - M1);
        const float4* hr = (const float4*)(hb + (size_t)n*kD);
        float in0 = 0.f, in1 = 0.f, in2 = 0.f, in3 = 0.f, in4 = 0.f;
        #pragma unroll 8
        for (int d4 = 0; d4 < 32; d4++) {
            float4 hv = __ldg(&hr[d4]);
            int dd = d4 * 4;
            in0 += hv.x*sqs[w][0][dd] + hv.y*sqs[w][0][dd+1] + hv.z*sqs[w][0][dd+2] + hv.w*sqs[w][0][dd+3];
            in1 += hv.x*sqs[w][1][dd] + hv.y*sqs[w][1][dd+1] + hv.z*sqs[w][1][dd+2] + hv.w*sqs[w][1][dd+3];
            in2 += hv.x*sqs[w][2][dd] + hv.y*sqs[w][2][dd+1] + hv.z*sqs[w][2][dd+2] + hv.w*sqs[w][2][dd+3];
            in3 += hv.x*sqs[w][3][dd] + hv.y*sqs[w][3][dd+1] + hv.z*sqs[w][3][dd+2] + hv.w*sqs[w][3][dd+3];
            in4 += hv.x*sqs[w][4][dd] + hv.y*sqs[w][4][dd+1] + hv.z*sqs[w][4][dd+2] + hv.w*sqs[w][4][dd+3];
        }
        float sv = r[0]*fast_sigmoid(in0) + r[1]*fast_sigmoid(in1) + r[2]*fast_sigmoid(in2)
                 + r[3]*fast_sigmoid(in3) + r[4]*fast_sigmoid(in4);
        sum_v += e * sv;
        sum_e += e;
    }
    #pragma unroll
    for (int o = 16; o; o >>= 1) {
        sum_v += __shfl_xor_sync(0xffffffffu, sum_v, o);
        sum_e += __shfl_xor_sync(0xffffffffu, sum_e, o);
    }
    if (lane == 0) {
        out[b*kS + t + 1] = sum_v / sum_e;
        if (t == 0) out[b*kS] = 0.f;
    }
}

// ---------------- launch ----------------
extern "C" void kernel_launch(void* const* d_in, const int* in_sizes, int n_in,
                              void* d_out, int out_size)
{
    const int*   question = (const int*)  d_in[0];
    const int*   response = (const int*)  d_in[1];
    const int*   q_nbr    = (const int*)  d_in[3];
    const int*   s_nbr    = (const int*)  d_in[4];
    const int*   qs_sk    = (const int*)  d_in[5];
    const float* emb_q    = (const float*)d_in[6];
    const float* emb_s    = (const float*)d_in[7];
    const float* emb_r    = (const float*)d_in[8];
    const float* W_ih     = (const float*)d_in[9];
    const float* b_ih     = (const float*)d_in[10];
    const float* b_hh     = (const float*)d_in[11];
    const float* ft_W     = (const float*)d_in[12];
    const float* ft_b     = (const float*)d_in[13];
    const float* agg_W    = (const float*)d_in[14];
    const float* agg_b    = (const float*)d_in[15];
    const float* last_W   = (const float*)d_in[16];
    const float* last_b   = (const float*)d_in[17];
    const float* q_W      = (const float*)d_in[18];
    const float* q_b      = (const float*)d_in[19];
    const float* k_W      = (const float*)d_in[20];
    const float* k_b      = (const float*)d_in[21];
    const float* w_W      = (const float*)d_in[22];
    float* out = (float*)d_out;

    float* buf = nullptr;
    cudaGetSymbolAddress((void**)&buf, g_buf);
    float* TA0 = buf + O_TA0;
    float* TA1 = buf + O_TA1;
    float* TA2 = buf + O_TA2;
    float* TB0 = buf + O_TB0;
    float* TB1 = buf + O_TB1;
    float* TC0 = buf + O_TA0;   // reuse: TA0 dead after level 1
    float* A   = buf + O_A;

    const int gq = (kNQ + 63) / 64;        // 157
    const int gs = (kNS + 63) / 64;        // 8
    const float iq = 1.f/kQN, is = 1.f/kSN;

    PrepArgs noprep = {}; noprep.enable = 0;
    HopTask zt = {};

    // level 0: TA0, TA2, TA1  (+ prep block)
    {
        HopParams p;
        p.nt = 3;
        p.t[0] = { emb_q, q_nbr, emb_s, agg_W,           agg_b,       TA0, kQN, iq, kNQ, 0 };
        p.t[1] = { emb_q, q_nbr, emb_s, agg_W + 2*16384, agg_b + 256, TA2, kQN, iq, kNQ, gq };
        p.t[2] = { emb_s, s_nbr, emb_q, agg_W + 16384,   agg_b + 128, TA1, kSN, is, kNS, 2*gq };
        p.prep = { q_W, q_b, k_W, k_b, w_W, emb_r, W_ih, b_ih, b_hh, 1 };
        hop_kernel<<<2*gq + gs + 1, 256>>>(p);
    }
    // level 1: TB0, TB1
    {
        HopParams p;
        p.nt = 2;
        p.t[0] = { TA0, q_nbr, TA1, agg_W,         agg_b,       TB0, kQN, iq, kNQ, 0 };
        p.t[1] = { TA1, s_nbr, TA2, agg_W + 16384, agg_b + 128, TB1, kSN, is, kNS, gq };
        p.t[2] = p.t[1];
        p.prep = noprep;
        hop_kernel<<<gq + gs, 256>>>(p);
    }
    // level 2: TC0 (reuses TA0 buffer)
    {
        HopParams p;
        p.nt = 1;
        p.t[0] = { TB0, q_nbr, TB1, agg_W, agg_b, TC0, kQN, iq, kNQ, 0 };
        p.t[1] = p.t[0]; p.t[2] = p.t[0];
        p.prep = noprep;
        hop_kernel<<<gq, 256>>>(p);
    }
    // last projection: A
    {
        HopParams p;
        p.nt = 1;
        p.t[0] = { TC0, nullptr, nullptr, last_W, last_b, A, 0, 0.f, kNQ, 0 };
        p.t[1] = p.t[0]; p.t[2] = p.t[0];
        p.prep = noprep;
        hop_kernel<<<gq, 256>>>(p);
    }

    // row chain (grid 200, 256 thr, ~17 KB smem)
    rowchain_kernel<<<(kB*kS)/32, 256>>>(question, response, ft_W, ft_b, W_ih);

    // pred: 8 warps/block share b
    dim3 pg((kT + 7) / 8, kB);
    pred_kernel<<<pg, 256>>>(question, qs_sk, emb_q, emb_s, out);
}

// round 9
// speedup vs baseline: 1.8210x; 1.8210x over previous
#include <cuda_runtime.h>
#include <math.h>
#include <stdint.h>

// ---------------- problem constants ----------------
#define kNQ 10000
#define kNS 500
#define kQN 4
#define kSN 10
#define kB  32
#define kS  200
#define kD  128
#define kT  199   // S-1

// ---------------- scratch layout (floats) ----------------
__host__ __device__ constexpr size_t O_TA0 = 0;                        // reused as TC0
__host__ __device__ constexpr size_t O_TA1 = O_TA0 + (size_t)kNQ*kD;
__host__ __device__ constexpr size_t O_TA2 = O_TA1 + (size_t)kNS*kD;
__host__ __device__ constexpr size_t O_TB0 = O_TA2 + (size_t)kNQ*kD;
__host__ __device__ constexpr size_t O_TB1 = O_TB0 + (size_t)kNQ*kD;
__host__ __device__ constexpr size_t O_A   = O_TB1 + (size_t)kNS*kD;
__host__ __device__ constexpr size_t O_H   = O_A   + (size_t)kNQ*kD;
__host__ __device__ constexpr size_t O_AS  = O_H   + (size_t)kB*kS*kD;
__host__ __device__ constexpr size_t O_V   = O_AS  + (size_t)kB*kT;   // qv[128], kv[128], c_q, c_k
__host__ __device__ constexpr size_t O_RG  = O_V   + 258;             // r_gates 2x512
__host__ __device__ constexpr size_t G_TOTAL = O_RG + 1024;

__device__ float g_buf[G_TOTAL];

// ---------------- fast math ----------------
__device__ __forceinline__ float fast_tanh(float x) {
    float y;
    asm("tanh.approx.f32 %0, %1;" : "=f"(y) : "f"(x));
    return y;
}
__device__ __forceinline__ float fast_sigmoid(float x) {
    return 0.5f * fast_tanh(0.5f * x) + 0.5f;
}

// ---------------- task structs ----------------
struct HopTask {
    const float* base;
    const int*   nbrs;
    const float* tbl;
    const float* W;      // 128x128 row-major
    const float* bias;
    float*       out;
    int knbr; float invk;
    int R; int blk0;     // blocks per task = 2*ceil(R/64) (column-split)
};
struct PrepArgs {
    const float *qW, *qb, *kW, *kb, *wW, *embr, *Wih, *bih, *bhh;
    int enable;
};
struct HopParams { HopTask t[3]; int nt; PrepArgs prep; };

// ---------------- hop kernel: 256 thr, 64 rows x 64 cols per block (column-split) ----------------
// smem: half-W 32KB + input tile 34KB = 66KB -> 3 blocks/SM.
__global__ __launch_bounds__(256, 3) void hop_kernel(const HopParams p)
{
    __shared__ float sW[kD*64];      // W[:, colbase:colbase+64], layout [k][64]
    __shared__ float sIn[64*132];
    const int tid = threadIdx.x;

    // prep block (independent side-work; consumers run kernels later)
    if (p.prep.enable && blockIdx.x == (int)gridDim.x - 1) {
        const PrepArgs& A = p.prep;
        float* vec = g_buf + O_V;
        float* rg  = g_buf + O_RG;
        if (tid < kD) {
            float sq = 0.f, sk = 0.f;
            #pragma unroll 4
            for (int j = 0; j < kD; j++) {
                sq += A.qW[tid*kD + j] * A.wW[j];
                sk += A.kW[tid*kD + j] * A.wW[kD + j];
            }
            vec[tid]      = sq;
            vec[kD + tid] = sk;
        }
        if (tid == 128) {
            float s = 0.f;
            for (int j = 0; j < kD; j++) s += A.qb[j] * A.wW[j];
            vec[256] = s;
        }
        if (tid == 129) {
            float s = 0.f;
            for (int j = 0; j < kD; j++) s += A.kb[j] * A.wW[kD + j];
            vec[257] = s;
        }
        for (int c = tid; c < 512; c += 256) {
            for (int r = 0; r < 2; r++) {
                float s = A.bih[c] + A.bhh[c];
                #pragma unroll 4
                for (int k = 0; k < kD; k++)
                    s += A.embr[r*kD + k] * A.Wih[(size_t)(kD + k)*512 + c];
                rg[r*512 + c] = s;
            }
        }
        return;
    }

    int ti = 0;
    #pragma unroll
    for (int i = 1; i < 3; i++)
        if (i < p.nt && (int)blockIdx.x >= p.t[i].blk0) ti = i;
    const HopTask& T = p.t[ti];
    const int local   = blockIdx.x - T.blk0;
    const int row0    = (local >> 1) * 64;
    const int colbase = (local & 1) * 64;

    // stage half of W: 128 k-rows x 64 cols = 2048 float4, 8 per thread
    {
        #pragma unroll
        for (int i = 0; i < 8; i++) {
            int idx = tid + i*256;           // 0..2047
            int k = idx >> 4, c4 = idx & 15; // 16 float4 per k-row
            *(float4*)(sW + k*64 + c4*4) =
                __ldg((const float4*)(T.W + (size_t)k*kD + colbase) + c4);
        }
    }

    // gather 64 rows (4 thr/row, 32 dims = 8 float4 each)
    {
        int lr = tid >> 2, part = tid & 3;
        int gr = row0 + lr;
        float4 v[8];
        if (gr < T.R) {
            const float4* bp = (const float4*)(T.base + (size_t)gr*kD) + part*8;
            #pragma unroll
            for (int d = 0; d < 8; d++) v[d] = __ldg(&bp[d]);
            if (T.knbr > 0) {
                float4 s[8];
                #pragma unroll
                for (int d = 0; d < 8; d++) s[d] = make_float4(0.f,0.f,0.f,0.f);
                for (int j = 0; j < T.knbr; j++) {
                    int nb = __ldg(&T.nbrs[(size_t)gr*T.knbr + j]);
                    const float4* tp = (const float4*)(T.tbl + (size_t)nb*kD) + part*8;
                    #pragma unroll
                    for (int d = 0; d < 8; d++) {
                        float4 x = __ldg(&tp[d]);
                        s[d].x += x.x; s[d].y += x.y; s[d].z += x.z; s[d].w += x.w;
                    }
                }
                #pragma unroll
                for (int d = 0; d < 8; d++) {
                    v[d].x += s[d].x * T.invk; v[d].y += s[d].y * T.invk;
                    v[d].z += s[d].z * T.invk; v[d].w += s[d].w * T.invk;
                }
            }
        } else {
            #pragma unroll
            for (int d = 0; d < 8; d++) v[d] = make_float4(0.f,0.f,0.f,0.f);
        }
        #pragma unroll
        for (int d = 0; d < 8; d++)
            *(float4*)(sIn + lr*132 + part*32 + d*4) = v[d];
    }
    __syncthreads();

    // 64x64 GEMM: thread tile 4 rows x 4 cols
    const int r0 = (tid >> 4) * 4;   // 0..60
    const int c0 = (tid & 15) * 4;   // 0..60 (within the 64-col half)
    float acc[4][4];
    #pragma unroll
    for (int i = 0; i < 4; i++)
        #pragma unroll
        for (int j = 0; j < 4; j++) acc[i][j] = 0.f;

    #pragma unroll 4
    for (int k = 0; k < kD; k++) {
        float a0 = sIn[(r0+0)*132 + k];
        float a1 = sIn[(r0+1)*132 + k];
        float a2 = sIn[(r0+2)*132 + k];
        float a3 = sIn[(r0+3)*132 + k];
        float4 b = *(const float4*)(sW + k*64 + c0);
        acc[0][0] += a0*b.x; acc[0][1] += a0*b.y; acc[0][2] += a0*b.z; acc[0][3] += a0*b.w;
        acc[1][0] += a1*b.x; acc[1][1] += a1*b.y; acc[1][2] += a1*b.z; acc[1][3] += a1*b.w;
        acc[2][0] += a2*b.x; acc[2][1] += a2*b.y; acc[2][2] += a2*b.z; acc[2][3] += a2*b.w;
        acc[3][0] += a3*b.x; acc[3][1] += a3*b.y; acc[3][2] += a3*b.z; acc[3][3] += a3*b.w;
    }

    float bsv[4];
    #pragma unroll
    for (int j = 0; j < 4; j++) bsv[j] = __ldg(&T.bias[colbase + c0 + j]);

    #pragma unroll
    for (int i = 0; i < 4; i++) {
        int gr = row0 + r0 + i;
        if (gr >= T.R) continue;
        float4 o;
        o.x = fast_tanh(acc[i][0] + bsv[0]);
        o.y = fast_tanh(acc[i][1] + bsv[1]);
        o.z = fast_tanh(acc[i][2] + bsv[2]);
        o.w = fast_tanh(acc[i][3] + bsv[3]);
        *(float4*)(T.out + (size_t)gr*kD + colbase + c0) = o;
    }
}

// ---------------- rowchain, wide-gates (R7 measured config): 512 thr, 64 rows ----------------
__global__ __launch_bounds__(512, 1) void rowchain_kernel(
    const int* __restrict__ question, const int* __restrict__ response,
    const float* __restrict__ ft_W, const float* __restrict__ ft_b,
    const float* __restrict__ W_ih)
{
    extern __shared__ float sm[];
    float* sW  = sm;                   // up to 3x 128x128
    float* sIn = sm + 3*kD*kD;         // 64x132
    float* sqv = sIn + 64*132;         // 128

    const float* A   = g_buf + O_A;
    const float* vec = g_buf + O_V;
    const float* RG  = g_buf + O_RG;
    float* H  = g_buf + O_H;
    float* AS = g_buf + O_AS;

    const int tid = threadIdx.x;
    const int row0 = blockIdx.x * 64;
    if (tid < kD) sqv[tid] = vec[tid];

    // gather A[question[row]] (8 threads/row, 16 dims = 4 float4)
    {
        int lr = tid >> 3, part = tid & 7;
        int grow = row0 + lr;
        int q = __ldg(&question[grow]);
        const float4* ap = (const float4*)(A + (size_t)q*kD) + part*4;
        #pragma unroll
        for (int d = 0; d < 4; d++)
            *(float4*)(sIn + lr*132 + part*16 + d*4) = __ldg(&ap[d]);
    }
    // load ft_W into sW[0:16384]
    {
        const float4* Wp = (const float4*)ft_W;
        #pragma unroll
        for (int i = 0; i < 8; i++)
            ((float4*)sW)[tid + i*512] = __ldg(&Wp[tid + i*512]);
    }
    __syncthreads();

    const int r0 = (tid >> 4) * 2;     // 0..62
    const int c0 = (tid & 15) * 8;     // 0..120

    // stage 1: QT = relu(in @ ft_W + ft_b)
    float acc[2][8];
    #pragma unroll
    for (int i = 0; i < 2; i++)
        #pragma unroll
        for (int j = 0; j < 8; j++) acc[i][j] = 0.f;
    #pragma unroll 4
    for (int k = 0; k < kD; k++) {
        float a0 = sIn[(r0+0)*132 + k];
        float a1 = sIn[(r0+1)*132 + k];
        float4 b0 = *(const float4*)(sW + k*kD + c0);
        float4 b1 = *(const float4*)(sW + k*kD + c0 + 4);
        float bb[8] = {b0.x,b0.y,b0.z,b0.w,b1.x,b1.y,b1.z,b1.w};
        #pragma unroll
        for (int j = 0; j < 8; j++) {
            acc[0][j] += a0*bb[j];
            acc[1][j] += a1*bb[j];
        }
    }
    float fb[8];
    #pragma unroll
    for (int j = 0; j < 8; j++) fb[j] = __ldg(&ft_b[c0 + j]);
    __syncthreads();                   // all GEMM reads of sIn/sW done
    #pragma unroll
    for (int i = 0; i < 2; i++)
        #pragma unroll
        for (int j = 0; j < 8; j++)
            sIn[(r0+i)*132 + c0 + j] = fmaxf(acc[i][j] + fb[j], 0.f);

    // load gate W slices: i=[0:128), g=[256:384), o=[384:512) of W_ih (128x512)
    {
        const int gofs[3] = {0, 256, 384};
        #pragma unroll
        for (int g = 0; g < 3; g++) {
            const float* Wg = W_ih + gofs[g];
            #pragma unroll
            for (int ii = 0; ii < 8; ii++) {
                int i = tid + ii*512;            // 0..4095
                int k = i >> 5, c4 = i & 31;
                ((float4*)(sW + g*16384 + k*kD))[c4] =
                    __ldg((const float4*)(Wg + (size_t)k*512) + c4);
            }
        }
    }
    __syncthreads();

    // stage 2: all three gates in one pass. Thread tile: 2 rows x (3 gates x 8 cols).
    float ai[2][8], ag[2][8], ao[2][8];
    #pragma unroll
    for (int i = 0; i < 2; i++)
        #pragma unroll
        for (int j = 0; j < 8; j++) { ai[i][j]=0.f; ag[i][j]=0.f; ao[i][j]=0.f; }

    #pragma unroll 2
    for (int k = 0; k < kD; k++) {
        float a0 = sIn[(r0+0)*132 + k];
        float a1 = sIn[(r0+1)*132 + k];
        float4 i0 = *(const float4*)(sW + 0*16384 + k*kD + c0);
        float4 i1 = *(const float4*)(sW + 0*16384 + k*kD + c0 + 4);
        float4 g0 = *(const float4*)(sW + 1*16384 + k*kD + c0);
        float4 g1 = *(const float4*)(sW + 1*16384 + k*kD + c0 + 4);
        float4 o0 = *(const float4*)(sW + 2*16384 + k*kD + c0);
        float4 o1 = *(const float4*)(sW + 2*16384 + k*kD + c0 + 4);
        float ib[8] = {i0.x,i0.y,i0.z,i0.w,i1.x,i1.y,i1.z,i1.w};
        float gb[8] = {g0.x,g0.y,g0.z,g0.w,g1.x,g1.y,g1.z,g1.w};
        float ob[8] = {o0.x,o0.y,o0.z,o0.w,o1.x,o1.y,o1.z,o1.w};
        #pragma unroll
        for (int j = 0; j < 8; j++) {
            ai[0][j] += a0*ib[j]; ai[1][j] += a1*ib[j];
            ag[0][j] += a0*gb[j]; ag[1][j] += a1*gb[j];
            ao[0][j] += a0*ob[j]; ao[1][j] += a1*ob[j];
        }
    }

    // epilogue: gates -> h (registers), write H, partial a_state
    const float cq = vec[256];
    #pragma unroll
    for (int i = 0; i < 2; i++) {
        int grow = row0 + r0 + i;
        int rr = __ldg(&response[grow]);
        const float* rgi = RG + rr*512 + 0   + c0;
        const float* rgg = RG + rr*512 + 256 + c0;
        const float* rgo = RG + rr*512 + 384 + c0;
        float hv[8];
        float p = 0.f;
        #pragma unroll
        for (int j = 0; j < 8; j++) {
            float iv = fast_sigmoid(ai[i][j] + rgi[j]);
            float gv = fast_tanh   (ag[i][j] + rgg[j]);
            float ov = fast_sigmoid(ao[i][j] + rgo[j]);
            hv[j] = ov * fast_tanh(iv * gv);
            p += hv[j] * sqv[c0 + j];
        }
        *(float4*)(H + (size_t)grow*kD + c0)     = make_float4(hv[0],hv[1],hv[2],hv[3]);
        *(float4*)(H + (size_t)grow*kD + c0 + 4) = make_float4(hv[4],hv[5],hv[6],hv[7]);
        p += __shfl_down_sync(0xffffffffu, p, 8, 16);
        p += __shfl_down_sync(0xffffffffu, p, 4, 16);
        p += __shfl_down_sync(0xffffffffu, p, 2, 16);
        p += __shfl_down_sync(0xffffffffu, p, 1, 16);
        if ((tid & 15) == 0) {
            int b = grow / kS, s = grow % kS;
            if (s < kT) AS[b*kT + s] = p + cq;
        }
    }
}

// ---------------- fused attention + prediction: one warp per (b,t) ----------------
__global__ __launch_bounds__(32, 24) void pred_kernel(
    const int* __restrict__ question,
    const int* __restrict__ qs_skills,
    const float* __restrict__ emb_q,
    const float* __restrict__ emb_s,
    float* __restrict__ out)
{
    const float* h   = g_buf + O_H;
    const float* as  = g_buf + O_AS;
    const float* vec = g_buf + O_V;

    __shared__ __align__(16) float sqs[5][kD];

    const int t = kT - 1 - blockIdx.x;     // big t first
    const int b = blockIdx.y;
    const int lane = threadIdx.x;

    int q = __ldg(&question[b*kS + t + 1]);
    ((float4*)sqs[0])[lane] = __ldg((const float4*)(emb_q + (size_t)q*kD) + lane);
    #pragma unroll
    for (int m = 1; m < 5; m++) {
        int si = __ldg(&qs_skills[q*4 + m - 1]);
        ((float4*)sqs[m])[lane] = __ldg((const float4*)(emb_s + (size_t)si*kD) + lane);
    }
    __syncwarp();

    // a_qs[m] = dot(sqs[m], kv); softmax over m (c_k cancels)
    float4 kv4 = *((const float4*)(vec + kD) + lane);
    float r[5];
    #pragma unroll
    for (int m = 0; m < 5; m++) {
        float4 s4 = ((float4*)sqs[m])[lane];
        float p = s4.x*kv4.x + s4.y*kv4.y + s4.z*kv4.z + s4.w*kv4.w;
        #pragma unroll
        for (int o = 16; o; o >>= 1) p += __shfl_xor_sync(0xffffffffu, p, o);
        r[m] = p;
    }
    {
        float mx = r[0];
        #pragma unroll
        for (int m = 1; m < 5; m++) mx = fmaxf(mx, r[m]);
        float se = 0.f;
        #pragma unroll
        for (int m = 0; m < 5; m++) { r[m] = __expf(r[m] - mx); se += r[m]; }
        float inv = __frcp_rn(se);
        #pragma unroll
        for (int m = 0; m < 5; m++) r[m] *= inv;
    }

    // max of a_state over n<=t
    float M1 = -1e30f;
    for (int n = lane; n <= t; n += 32) M1 = fmaxf(M1, as[b*kT + n]);
    #pragma unroll
    for (int o = 16; o; o >>= 1) M1 = fmaxf(M1, __shfl_xor_sync(0xffffffffu, M1, o));

    float sum_v = 0.f, sum_e = 0.f;
    for (int n = lane; n <= t; n += 32) {
        float e = __expf(as[b*kT + n] - M1);
        const float4* hr = (const float4*)(h + ((size_t)b*kS + n)*kD);
        float in0 = 0.f, in1 = 0.f, in2 = 0.f, in3 = 0.f, in4 = 0.f;
        #pragma unroll 8
        for (int d4 = 0; d4 < 32; d4++) {
            float4 hv = __ldg(&hr[d4]);
            int dd = d4 * 4;
            in0 += hv.x*sqs[0][dd] + hv.y*sqs[0][dd+1] + hv.z*sqs[0][dd+2] + hv.w*sqs[0][dd+3];
            in1 += hv.x*sqs[1][dd] + hv.y*sqs[1][dd+1] + hv.z*sqs[1][dd+2] + hv.w*sqs[1][dd+3];
            in2 += hv.x*sqs[2][dd] + hv.y*sqs[2][dd+1] + hv.z*sqs[2][dd+2] + hv.w*sqs[2][dd+3];
            in3 += hv.x*sqs[3][dd] + hv.y*sqs[3][dd+1] + hv.z*sqs[3][dd+2] + hv.w*sqs[3][dd+3];
            in4 += hv.x*sqs[4][dd] + hv.y*sqs[4][dd+1] + hv.z*sqs[4][dd+2] + hv.w*sqs[4][dd+3];
        }
        float sv = r[0]*fast_sigmoid(in0) + r[1]*fast_sigmoid(in1) + r[2]*fast_sigmoid(in2)
                 + r[3]*fast_sigmoid(in3) + r[4]*fast_sigmoid(in4);
        sum_v += e * sv;
        sum_e += e;
    }
    #pragma unroll
    for (int o = 16; o; o >>= 1) {
        sum_v += __shfl_xor_sync(0xffffffffu, sum_v, o);
        sum_e += __shfl_xor_sync(0xffffffffu, sum_e, o);
    }
    if (lane == 0) {
        out[b*kS + t + 1] = sum_v / sum_e;
        if (t == 0) out[b*kS] = 0.f;
    }
}

// ---------------- launch ----------------
extern "C" void kernel_launch(void* const* d_in, const int* in_sizes, int n_in,
                              void* d_out, int out_size)
{
    const int*   question = (const int*)  d_in[0];
    const int*   response = (const int*)  d_in[1];
    const int*   q_nbr    = (const int*)  d_in[3];
    const int*   s_nbr    = (const int*)  d_in[4];
    const int*   qs_sk    = (const int*)  d_in[5];
    const float* emb_q    = (const float*)d_in[6];
    const float* emb_s    = (const float*)d_in[7];
    const float* emb_r    = (const float*)d_in[8];
    const float* W_ih     = (const float*)d_in[9];
    const float* b_ih     = (const float*)d_in[10];
    const float* b_hh     = (const float*)d_in[11];
    const float* ft_W     = (const float*)d_in[12];
    const float* ft_b     = (const float*)d_in[13];
    const float* agg_W    = (const float*)d_in[14];
    const float* agg_b    = (const float*)d_in[15];
    const float* last_W   = (const float*)d_in[16];
    const float* last_b   = (const float*)d_in[17];
    const float* q_W      = (const float*)d_in[18];
    const float* q_b      = (const float*)d_in[19];
    const float* k_W      = (const float*)d_in[20];
    const float* k_b      = (const float*)d_in[21];
    const float* w_W      = (const float*)d_in[22];
    float* out = (float*)d_out;

    float* buf = nullptr;
    cudaGetSymbolAddress((void**)&buf, g_buf);
    float* TA0 = buf + O_TA0;
    float* TA1 = buf + O_TA1;
    float* TA2 = buf + O_TA2;
    float* TB0 = buf + O_TB0;
    float* TB1 = buf + O_TB1;
    float* TC0 = buf + O_TA0;   // reuse: TA0 dead after level 1
    float* A   = buf + O_A;

    const int RC_SMEM = (3*kD*kD + 64*132 + 128) * (int)sizeof(float);
    static bool attr_done = false;
    if (!attr_done) {
        cudaFuncSetAttribute(rowchain_kernel, cudaFuncAttributeMaxDynamicSharedMemorySize, RC_SMEM);
        attr_done = true;
    }

    const int gq = 2 * ((kNQ + 63) / 64);  // 314 (column-split)
    const int gs = 2 * ((kNS + 63) / 64);  // 16
    const float iq = 1.f/kQN, is = 1.f/kSN;

    PrepArgs noprep = {}; noprep.enable = 0;

    // level 0: TA0, TA2, TA1  (+ prep block)
    {
        HopParams p;
        p.nt = 3;
        p.t[0] = { emb_q, q_nbr, emb_s, agg_W,           agg_b,       TA0, kQN, iq, kNQ, 0 };
        p.t[1] = { emb_q, q_nbr, emb_s, agg_W + 2*16384, agg_b + 256, TA2, kQN, iq, kNQ, gq };
        p.t[2] = { emb_s, s_nbr, emb_q, agg_W + 16384,   agg_b + 128, TA1, kSN, is, kNS, 2*gq };
        p.prep = { q_W, q_b, k_W, k_b, w_W, emb_r, W_ih, b_ih, b_hh, 1 };
        hop_kernel<<<2*gq + gs + 1, 256>>>(p);
    }
    // level 1: TB0, TB1
    {
        HopParams p;
        p.nt = 2;
        p.t[0] = { TA0, q_nbr, TA1, agg_W,         agg_b,       TB0, kQN, iq, kNQ, 0 };
        p.t[1] = { TA1, s_nbr, TA2, agg_W + 16384, agg_b + 128, TB1, kSN, is, kNS, gq };
        p.t[2] = p.t[1];
        p.prep = noprep;
        hop_kernel<<<gq + gs, 256>>>(p);
    }
    // level 2: TC0 (reuses TA0 buffer)
    {
        HopParams p;
        p.nt = 1;
        p.t[0] = { TB0, q_nbr, TB1, agg_W, agg_b, TC0, kQN, iq, kNQ, 0 };
        p.t[1] = p.t[0]; p.t[2] = p.t[0];
        p.prep = noprep;
        hop_kernel<<<gq, 256>>>(p);
    }
    // last projection: A
    {
        HopParams p;
        p.nt = 1;
        p.t[0] = { TC0, nullptr, nullptr, last_W, last_b, A, 0, 0.f, kNQ, 0 };
        p.t[1] = p.t[0]; p.t[2] = p.t[0];
        p.prep = noprep;
        hop_kernel<<<gq, 256>>>(p);
    }

    // row chain: wide gates (grid 100, 512 thr, ~226 KB smem)
    rowchain_kernel<<<(kB*kS)/64, 512, RC_SMEM>>>(question, response, ft_W, ft_b, W_ih);

    dim3 pg(kT, kB);
    pred_kernel<<<pg, 32>>>(question, qs_sk, emb_q, emb_s, out);
}

// round 10
// speedup vs baseline: 2.2659x; 1.2443x over previous
#include <cuda_runtime.h>
#include <math.h>
#include <stdint.h>

// ---------------- problem constants ----------------
#define kNQ 10000
#define kNS 500
#define kQN 4
#define kSN 10
#define kB  32
#define kS  200
#define kD  128
#define kT  199   // S-1

// ---------------- scratch layout (floats) ----------------
__host__ __device__ constexpr size_t O_TA0 = 0;                        // reused as TC0
__host__ __device__ constexpr size_t O_TA1 = O_TA0 + (size_t)kNQ*kD;
__host__ __device__ constexpr size_t O_TA2 = O_TA1 + (size_t)kNS*kD;
__host__ __device__ constexpr size_t O_TB0 = O_TA2 + (size_t)kNQ*kD;
__host__ __device__ constexpr size_t O_TB1 = O_TB0 + (size_t)kNQ*kD;
__host__ __device__ constexpr size_t O_A   = O_TB1 + (size_t)kNS*kD;
__host__ __device__ constexpr size_t O_H   = O_A   + (size_t)kNQ*kD;  // Ht: [b][d][s] transposed
__host__ __device__ constexpr size_t O_AS  = O_H   + (size_t)kB*kS*kD;
__host__ __device__ constexpr size_t O_V   = O_AS  + (size_t)kB*kT;   // qv[128], kv[128], c_q, c_k
__host__ __device__ constexpr size_t O_RG  = O_V   + 258;             // r_gates 2x512
__host__ __device__ constexpr size_t G_TOTAL = O_RG + 1024;

__device__ float g_buf[G_TOTAL];

// ---------------- fast math ----------------
__device__ __forceinline__ float fast_tanh(float x) {
    float y;
    asm("tanh.approx.f32 %0, %1;" : "=f"(y) : "f"(x));
    return y;
}
__device__ __forceinline__ float fast_sigmoid(float x) {
    return 0.5f * fast_tanh(0.5f * x) + 0.5f;
}

// ---------------- task structs ----------------
struct HopTask {
    const float* base;
    const int*   nbrs;
    const float* tbl;
    const float* W;      // 128x128 row-major
    const float* bias;
    float*       out;
    int knbr; float invk;
    int R; int blk0;     // blocks per task = 2*ceil(R/64) (column-split)
};
struct PrepArgs {
    const float *qW, *qb, *kW, *kb, *wW, *embr, *Wih, *bih, *bhh;
    int enable;
};
struct HopParams { HopTask t[3]; int nt; PrepArgs prep; };

// ---------------- hop kernel: 256 thr, 64 rows x 64 cols per block (column-split) ----------------
__global__ __launch_bounds__(256, 3) void hop_kernel(const HopParams p)
{
    __shared__ float sW[kD*64];      // W[:, colbase:colbase+64], layout [k][64]
    __shared__ float sIn[64*132];
    const int tid = threadIdx.x;

    // prep block (independent side-work; consumers run kernels later)
    if (p.prep.enable && blockIdx.x == (int)gridDim.x - 1) {
        const PrepArgs& A = p.prep;
        float* vec = g_buf + O_V;
        float* rg  = g_buf + O_RG;
        if (tid < kD) {
            float sq = 0.f, sk = 0.f;
            #pragma unroll 4
            for (int j = 0; j < kD; j++) {
                sq += A.qW[tid*kD + j] * A.wW[j];
                sk += A.kW[tid*kD + j] * A.wW[kD + j];
            }
            vec[tid]      = sq;
            vec[kD + tid] = sk;
        }
        if (tid == 128) {
            float s = 0.f;
            for (int j = 0; j < kD; j++) s += A.qb[j] * A.wW[j];
            vec[256] = s;
        }
        if (tid == 129) {
            float s = 0.f;
            for (int j = 0; j < kD; j++) s += A.kb[j] * A.wW[kD + j];
            vec[257] = s;
        }
        for (int c = tid; c < 512; c += 256) {
            for (int r = 0; r < 2; r++) {
                float s = A.bih[c] + A.bhh[c];
                #pragma unroll 4
                for (int k = 0; k < kD; k++)
                    s += A.embr[r*kD + k] * A.Wih[(size_t)(kD + k)*512 + c];
                rg[r*512 + c] = s;
            }
        }
        return;
    }

    int ti = 0;
    #pragma unroll
    for (int i = 1; i < 3; i++)
        if (i < p.nt && (int)blockIdx.x >= p.t[i].blk0) ti = i;
    const HopTask& T = p.t[ti];
    const int local   = blockIdx.x - T.blk0;
    const int row0    = (local >> 1) * 64;
    const int colbase = (local & 1) * 64;

    // stage half of W: 128 k-rows x 64 cols = 2048 float4, 8 per thread
    {
        #pragma unroll
        for (int i = 0; i < 8; i++) {
            int idx = tid + i*256;           // 0..2047
            int k = idx >> 4, c4 = idx & 15; // 16 float4 per k-row
            *(float4*)(sW + k*64 + c4*4) =
                __ldg((const float4*)(T.W + (size_t)k*kD + colbase) + c4);
        }
    }

    // gather 64 rows (4 thr/row, 32 dims = 8 float4 each)
    {
        int lr = tid >> 2, part = tid & 3;
        int gr = row0 + lr;
        float4 v[8];
        if (gr < T.R) {
            const float4* bp = (const float4*)(T.base + (size_t)gr*kD) + part*8;
            #pragma unroll
            for (int d = 0; d < 8; d++) v[d] = __ldg(&bp[d]);
            if (T.knbr > 0) {
                float4 s[8];
                #pragma unroll
                for (int d = 0; d < 8; d++) s[d] = make_float4(0.f,0.f,0.f,0.f);
                for (int j = 0; j < T.knbr; j++) {
                    int nb = __ldg(&T.nbrs[(size_t)gr*T.knbr + j]);
                    const float4* tp = (const float4*)(T.tbl + (size_t)nb*kD) + part*8;
                    #pragma unroll
                    for (int d = 0; d < 8; d++) {
                        float4 x = __ldg(&tp[d]);
                        s[d].x += x.x; s[d].y += x.y; s[d].z += x.z; s[d].w += x.w;
                    }
                }
                #pragma unroll
                for (int d = 0; d < 8; d++) {
                    v[d].x += s[d].x * T.invk; v[d].y += s[d].y * T.invk;
                    v[d].z += s[d].z * T.invk; v[d].w += s[d].w * T.invk;
                }
            }
        } else {
            #pragma unroll
            for (int d = 0; d < 8; d++) v[d] = make_float4(0.f,0.f,0.f,0.f);
        }
        #pragma unroll
        for (int d = 0; d < 8; d++)
            *(float4*)(sIn + lr*132 + part*32 + d*4) = v[d];
    }
    __syncthreads();

    // 64x64 GEMM: thread tile 4 rows x 4 cols
    const int r0 = (tid >> 4) * 4;
    const int c0 = (tid & 15) * 4;
    float acc[4][4];
    #pragma unroll
    for (int i = 0; i < 4; i++)
        #pragma unroll
        for (int j = 0; j < 4; j++) acc[i][j] = 0.f;

    #pragma unroll 4
    for (int k = 0; k < kD; k++) {
        float a0 = sIn[(r0+0)*132 + k];
        float a1 = sIn[(r0+1)*132 + k];
        float a2 = sIn[(r0+2)*132 + k];
        float a3 = sIn[(r0+3)*132 + k];
        float4 b = *(const float4*)(sW + k*64 + c0);
        acc[0][0] += a0*b.x; acc[0][1] += a0*b.y; acc[0][2] += a0*b.z; acc[0][3] += a0*b.w;
        acc[1][0] += a1*b.x; acc[1][1] += a1*b.y; acc[1][2] += a1*b.z; acc[1][3] += a1*b.w;
        acc[2][0] += a2*b.x; acc[2][1] += a2*b.y; acc[2][2] += a2*b.z; acc[2][3] += a2*b.w;
        acc[3][0] += a3*b.x; acc[3][1] += a3*b.y; acc[3][2] += a3*b.z; acc[3][3] += a3*b.w;
    }

    float bsv[4];
    #pragma unroll
    for (int j = 0; j < 4; j++) bsv[j] = __ldg(&T.bias[colbase + c0 + j]);

    #pragma unroll
    for (int i = 0; i < 4; i++) {
        int gr = row0 + r0 + i;
        if (gr >= T.R) continue;
        float4 o;
        o.x = fast_tanh(acc[i][0] + bsv[0]);
        o.y = fast_tanh(acc[i][1] + bsv[1]);
        o.z = fast_tanh(acc[i][2] + bsv[2]);
        o.w = fast_tanh(acc[i][3] + bsv[3]);
        *(float4*)(T.out + (size_t)gr*kD + colbase + c0) = o;
    }
}

// ---------------- rowchain, wide-gates: 512 thr, 64 rows; writes TRANSPOSED Ht ----------------
__global__ __launch_bounds__(512, 1) void rowchain_kernel(
    const int* __restrict__ question, const int* __restrict__ response,
    const float* __restrict__ ft_W, const float* __restrict__ ft_b,
    const float* __restrict__ W_ih)
{
    extern __shared__ float sm[];
    float* sW  = sm;                   // up to 3x 128x128
    float* sIn = sm + 3*kD*kD;         // 64x132
    float* sqv = sIn + 64*132;         // 128

    const float* A   = g_buf + O_A;
    const float* vec = g_buf + O_V;
    const float* RG  = g_buf + O_RG;
    float* Ht = g_buf + O_H;
    float* AS = g_buf + O_AS;

    const int tid = threadIdx.x;
    const int row0 = blockIdx.x * 64;
    if (tid < kD) sqv[tid] = vec[tid];

    // gather A[question[row]] (8 threads/row, 16 dims = 4 float4)
    {
        int lr = tid >> 3, part = tid & 7;
        int grow = row0 + lr;
        int q = __ldg(&question[grow]);
        const float4* ap = (const float4*)(A + (size_t)q*kD) + part*4;
        #pragma unroll
        for (int d = 0; d < 4; d++)
            *(float4*)(sIn + lr*132 + part*16 + d*4) = __ldg(&ap[d]);
    }
    // load ft_W into sW[0:16384]
    {
        const float4* Wp = (const float4*)ft_W;
        #pragma unroll
        for (int i = 0; i < 8; i++)
            ((float4*)sW)[tid + i*512] = __ldg(&Wp[tid + i*512]);
    }
    __syncthreads();

    const int r0 = (tid >> 4) * 2;     // 0..62
    const int c0 = (tid & 15) * 8;     // 0..120

    // stage 1: QT = relu(in @ ft_W + ft_b)
    float acc[2][8];
    #pragma unroll
    for (int i = 0; i < 2; i++)
        #pragma unroll
        for (int j = 0; j < 8; j++) acc[i][j] = 0.f;
    #pragma unroll 4
    for (int k = 0; k < kD; k++) {
        float a0 = sIn[(r0+0)*132 + k];
        float a1 = sIn[(r0+1)*132 + k];
        float4 b0 = *(const float4*)(sW + k*kD + c0);
        float4 b1 = *(const float4*)(sW + k*kD + c0 + 4);
        float bb[8] = {b0.x,b0.y,b0.z,b0.w,b1.x,b1.y,b1.z,b1.w};
        #pragma unroll
        for (int j = 0; j < 8; j++) {
            acc[0][j] += a0*bb[j];
            acc[1][j] += a1*bb[j];
        }
    }
    float fb[8];
    #pragma unroll
    for (int j = 0; j < 8; j++) fb[j] = __ldg(&ft_b[c0 + j]);
    __syncthreads();                   // all GEMM reads of sIn/sW done
    #pragma unroll
    for (int i = 0; i < 2; i++)
        #pragma unroll
        for (int j = 0; j < 8; j++)
            sIn[(r0+i)*132 + c0 + j] = fmaxf(acc[i][j] + fb[j], 0.f);

    // load gate W slices: i=[0:128), g=[256:384), o=[384:512) of W_ih (128x512)
    {
        const int gofs[3] = {0, 256, 384};
        #pragma unroll
        for (int g = 0; g < 3; g++) {
            const float* Wg = W_ih + gofs[g];
            #pragma unroll
            for (int ii = 0; ii < 8; ii++) {
                int i = tid + ii*512;            // 0..4095
                int k = i >> 5, c4 = i & 31;
                ((float4*)(sW + g*16384 + k*kD))[c4] =
                    __ldg((const float4*)(Wg + (size_t)k*512) + c4);
            }
        }
    }
    __syncthreads();

    // stage 2: all three gates in one pass. Thread tile: 2 rows x (3 gates x 8 cols).
    float ai[2][8], ag[2][8], ao[2][8];
    #pragma unroll
    for (int i = 0; i < 2; i++)
        #pragma unroll
        for (int j = 0; j < 8; j++) { ai[i][j]=0.f; ag[i][j]=0.f; ao[i][j]=0.f; }

    #pragma unroll 2
    for (int k = 0; k < kD; k++) {
        float a0 = sIn[(r0+0)*132 + k];
        float a1 = sIn[(r0+1)*132 + k];
        float4 i0 = *(const float4*)(sW + 0*16384 + k*kD + c0);
        float4 i1 = *(const float4*)(sW + 0*16384 + k*kD + c0 + 4);
        float4 g0 = *(const float4*)(sW + 1*16384 + k*kD + c0);
        float4 g1 = *(const float4*)(sW + 1*16384 + k*kD + c0 + 4);
        float4 o0 = *(const float4*)(sW + 2*16384 + k*kD + c0);
        float4 o1 = *(const float4*)(sW + 2*16384 + k*kD + c0 + 4);
        float ib[8] = {i0.x,i0.y,i0.z,i0.w,i1.x,i1.y,i1.z,i1.w};
        float gb[8] = {g0.x,g0.y,g0.z,g0.w,g1.x,g1.y,g1.z,g1.w};
        float ob[8] = {o0.x,o0.y,o0.z,o0.w,o1.x,o1.y,o1.z,o1.w};
        #pragma unroll
        for (int j = 0; j < 8; j++) {
            ai[0][j] += a0*ib[j]; ai[1][j] += a1*ib[j];
            ag[0][j] += a0*gb[j]; ag[1][j] += a1*gb[j];
            ao[0][j] += a0*ob[j]; ao[1][j] += a1*ob[j];
        }
    }

    // epilogue: gates -> h (registers), write TRANSPOSED Ht[b][d][s], partial a_state
    const float cq = vec[256];
    #pragma unroll
    for (int i = 0; i < 2; i++) {
        int grow = row0 + r0 + i;
        int rr = __ldg(&response[grow]);
        int bb2 = grow / kS, ss = grow % kS;
        const float* rgi = RG + rr*512 + 0   + c0;
        const float* rgg = RG + rr*512 + 256 + c0;
        const float* rgo = RG + rr*512 + 384 + c0;
        float hv[8];
        float p = 0.f;
        #pragma unroll
        for (int j = 0; j < 8; j++) {
            float iv = fast_sigmoid(ai[i][j] + rgi[j]);
            float gv = fast_tanh   (ag[i][j] + rgg[j]);
            float ov = fast_sigmoid(ao[i][j] + rgo[j]);
            hv[j] = ov * fast_tanh(iv * gv);
            p += hv[j] * sqv[c0 + j];
        }
        #pragma unroll
        for (int j = 0; j < 8; j++)
            Ht[((size_t)bb2*kD + c0 + j)*kS + ss] = hv[j];
        p += __shfl_down_sync(0xffffffffu, p, 8, 16);
        p += __shfl_down_sync(0xffffffffu, p, 4, 16);
        p += __shfl_down_sync(0xffffffffu, p, 2, 16);
        p += __shfl_down_sync(0xffffffffu, p, 1, 16);
        if ((tid & 15) == 0) {
            if (ss < kT) AS[bb2*kT + ss] = p + cq;
        }
    }
}

// ---------------- pred: one warp per (b,t); lane owns 4 consecutive n (coalesced Ht) ----------------
__global__ __launch_bounds__(32, 24) void pred_kernel(
    const int* __restrict__ question,
    const int* __restrict__ qs_skills,
    const float* __restrict__ emb_q,
    const float* __restrict__ emb_s,
    float* __restrict__ out)
{
    const float* Ht  = g_buf + O_H;
    const float* as  = g_buf + O_AS;
    const float* vec = g_buf + O_V;

    __shared__ __align__(16) float sqs[5][kD];

    const int t = kT - 1 - blockIdx.x;     // big t first
    const int b = blockIdx.y;
    const int lane = threadIdx.x;

    int q = __ldg(&question[b*kS + t + 1]);
    ((float4*)sqs[0])[lane] = __ldg((const float4*)(emb_q + (size_t)q*kD) + lane);
    #pragma unroll
    for (int m = 1; m < 5; m++) {
        int si = __ldg(&qs_skills[q*4 + m - 1]);
        ((float4*)sqs[m])[lane] = __ldg((const float4*)(emb_s + (size_t)si*kD) + lane);
    }
    __syncwarp();

    // a_qs[m] = dot(sqs[m], kv); softmax over m (c_k cancels)
    float4 kv4 = *((const float4*)(vec + kD) + lane);
    float r[5];
    #pragma unroll
    for (int m = 0; m < 5; m++) {
        float4 s4 = ((float4*)sqs[m])[lane];
        float p = s4.x*kv4.x + s4.y*kv4.y + s4.z*kv4.z + s4.w*kv4.w;
        #pragma unroll
        for (int o = 16; o; o >>= 1) p += __shfl_xor_sync(0xffffffffu, p, o);
        r[m] = p;
    }
    {
        float mx = r[0];
        #pragma unroll
        for (int m = 1; m < 5; m++) mx = fmaxf(mx, r[m]);
        float se = 0.f;
        #pragma unroll
        for (int m = 0; m < 5; m++) { r[m] = __expf(r[m] - mx); se += r[m]; }
        float inv = __frcp_rn(se);
        #pragma unroll
        for (int m = 0; m < 5; m++) r[m] *= inv;
    }

    const float* asb = as + b*kT;

    // max of a_state over n<=t
    float M1 = -1e30f;
    for (int n = lane; n <= t; n += 32) M1 = fmaxf(M1, asb[n]);
    #pragma unroll
    for (int o = 16; o; o >>= 1) M1 = fmaxf(M1, __shfl_xor_sync(0xffffffffu, M1, o));

    const float* hb = Ht + (size_t)b*kD*kS;
    float sum_v = 0.f, sum_e = 0.f;

    for (int base = 0; base <= t; base += 128) {
        const int n0 = base + lane*4;
        const float* hcol = hb + n0;
        float a0[4] = {0.f,0.f,0.f,0.f};
        float a1[4] = {0.f,0.f,0.f,0.f};
        float a2[4] = {0.f,0.f,0.f,0.f};
        float a3[4] = {0.f,0.f,0.f,0.f};
        float a4[4] = {0.f,0.f,0.f,0.f};

        #pragma unroll 2
        for (int d = 0; d < kD; d += 4) {
            float4 s0 = *(const float4*)&sqs[0][d];
            float4 s1 = *(const float4*)&sqs[1][d];
            float4 s2 = *(const float4*)&sqs[2][d];
            float4 s3 = *(const float4*)&sqs[3][d];
            float4 s4 = *(const float4*)&sqs[4][d];
            #pragma unroll
            for (int dd = 0; dd < 4; dd++) {
                float4 hv = *(const float4*)(hcol + (size_t)(d + dd)*kS);
                float c0v = (&s0.x)[dd];
                float c1v = (&s1.x)[dd];
                float c2v = (&s2.x)[dd];
                float c3v = (&s3.x)[dd];
                float c4v = (&s4.x)[dd];
                a0[0] += hv.x*c0v; a0[1] += hv.y*c0v; a0[2] += hv.z*c0v; a0[3] += hv.w*c0v;
                a1[0] += hv.x*c1v; a1[1] += hv.y*c1v; a1[2] += hv.z*c1v; a1[3] += hv.w*c1v;
                a2[0] += hv.x*c2v; a2[1] += hv.y*c2v; a2[2] += hv.z*c2v; a2[3] += hv.w*c2v;
                a3[0] += hv.x*c3v; a3[1] += hv.y*c3v; a3[2] += hv.z*c3v; a3[3] += hv.w*c3v;
                a4[0] += hv.x*c4v; a4[1] += hv.y*c4v; a4[2] += hv.z*c4v; a4[3] += hv.w*c4v;
            }
        }

        #pragma unroll
        for (int j = 0; j < 4; j++) {
            int n = n0 + j;
            if (n <= t) {
                float e = __expf(asb[n] - M1);
                float sv = r[0]*fast_sigmoid(a0[j]) + r[1]*fast_sigmoid(a1[j])
                         + r[2]*fast_sigmoid(a2[j]) + r[3]*fast_sigmoid(a3[j])
                         + r[4]*fast_sigmoid(a4[j]);
                sum_v += e * sv;
                sum_e += e;
            }
        }
    }
    #pragma unroll
    for (int o = 16; o; o >>= 1) {
        sum_v += __shfl_xor_sync(0xffffffffu, sum_v, o);
        sum_e += __shfl_xor_sync(0xffffffffu, sum_e, o);
    }
    if (lane == 0) {
        out[b*kS + t + 1] = sum_v / sum_e;
        if (t == 0) out[b*kS] = 0.f;
    }
}

// ---------------- launch ----------------
extern "C" void kernel_launch(void* const* d_in, const int* in_sizes, int n_in,
                              void* d_out, int out_size)
{
    const int*   question = (const int*)  d_in[0];
    const int*   response = (const int*)  d_in[1];
    const int*   q_nbr    = (const int*)  d_in[3];
    const int*   s_nbr    = (const int*)  d_in[4];
    const int*   qs_sk    = (const int*)  d_in[5];
    const float* emb_q    = (const float*)d_in[6];
    const float* emb_s    = (const float*)d_in[7];
    const float* emb_r    = (const float*)d_in[8];
    const float* W_ih     = (const float*)d_in[9];
    const float* b_ih     = (const float*)d_in[10];
    const float* b_hh     = (const float*)d_in[11];
    const float* ft_W     = (const float*)d_in[12];
    const float* ft_b     = (const float*)d_in[13];
    const float* agg_W    = (const float*)d_in[14];
    const float* agg_b    = (const float*)d_in[15];
    const float* last_W   = (const float*)d_in[16];
    const float* last_b   = (const float*)d_in[17];
    const float* q_W      = (const float*)d_in[18];
    const float* q_b      = (const float*)d_in[19];
    const float* k_W      = (const float*)d_in[20];
    const float* k_b      = (const float*)d_in[21];
    const float* w_W      = (const float*)d_in[22];
    float* out = (float*)d_out;

    float* buf = nullptr;
    cudaGetSymbolAddress((void**)&buf, g_buf);
    float* TA0 = buf + O_TA0;
    float* TA1 = buf + O_TA1;
    float* TA2 = buf + O_TA2;
    float* TB0 = buf + O_TB0;
    float* TB1 = buf + O_TB1;
    float* TC0 = buf + O_TA0;   // reuse: TA0 dead after level 1
    float* A   = buf + O_A;

    const int RC_SMEM = (3*kD*kD + 64*132 + 128) * (int)sizeof(float);
    static bool attr_done = false;
    if (!attr_done) {
        cudaFuncSetAttribute(rowchain_kernel, cudaFuncAttributeMaxDynamicSharedMemorySize, RC_SMEM);
        attr_done = true;
    }

    const int gq = 2 * ((kNQ + 63) / 64);  // 314 (column-split)
    const int gs = 2 * ((kNS + 63) / 64);  // 16
    const float iq = 1.f/kQN, is = 1.f/kSN;

    PrepArgs noprep = {}; noprep.enable = 0;

    // level 0: TA0, TA2, TA1  (+ prep block)
    {
        HopParams p;
        p.nt = 3;
        p.t[0] = { emb_q, q_nbr, emb_s, agg_W,           agg_b,       TA0, kQN, iq, kNQ, 0 };
        p.t[1] = { emb_q, q_nbr, emb_s, agg_W + 2*16384, agg_b + 256, TA2, kQN, iq, kNQ, gq };
        p.t[2] = { emb_s, s_nbr, emb_q, agg_W + 16384,   agg_b + 128, TA1, kSN, is, kNS, 2*gq };
        p.prep = { q_W, q_b, k_W, k_b, w_W, emb_r, W_ih, b_ih, b_hh, 1 };
        hop_kernel<<<2*gq + gs + 1, 256>>>(p);
    }
    // level 1: TB0, TB1
    {
        HopParams p;
        p.nt = 2;
        p.t[0] = { TA0, q_nbr, TA1, agg_W,         agg_b,       TB0, kQN, iq, kNQ, 0 };
        p.t[1] = { TA1, s_nbr, TA2, agg_W + 16384, agg_b + 128, TB1, kSN, is, kNS, gq };
        p.t[2] = p.t[1];
        p.prep = noprep;
        hop_kernel<<<gq + gs, 256>>>(p);
    }
    // level 2: TC0 (reuses TA0 buffer)
    {
        HopParams p;
        p.nt = 1;
        p.t[0] = { TB0, q_nbr, TB1, agg_W, agg_b, TC0, kQN, iq, kNQ, 0 };
        p.t[1] = p.t[0]; p.t[2] = p.t[0];
        p.prep = noprep;
        hop_kernel<<<gq, 256>>>(p);
    }
    // last projection: A
    {
        HopParams p;
        p.nt = 1;
        p.t[0] = { TC0, nullptr, nullptr, last_W, last_b, A, 0, 0.f, kNQ, 0 };
        p.t[1] = p.t[0]; p.t[2] = p.t[0];
        p.prep = noprep;
        hop_kernel<<<gq, 256>>>(p);
    }

    // row chain: wide gates (grid 100, 512 thr, ~226 KB smem) -> Ht transposed + AS
    rowchain_kernel<<<(kB*kS)/64, 512, RC_SMEM>>>(question, response, ft_W, ft_b, W_ih);

    dim3 pg(kT, kB);
    pred_kernel<<<pg, 32>>>(question, qs_sk, emb_q, emb_s, out);
}

// round 11
// speedup vs baseline: 2.6174x; 1.1551x over previous
#include <cuda_runtime.h>
#include <math.h>
#include <stdint.h>

// ---------------- problem constants ----------------
#define kNQ 10000
#define kNS 500
#define kQN 4
#define kSN 10
#define kB  32
#define kS  200
#define kD  128
#define kT  199   // S-1

// ---------------- scratch layout (floats) ----------------
__host__ __device__ constexpr size_t O_TA0 = 0;                        // reused: TC0, then G
__host__ __device__ constexpr size_t O_TA1 = O_TA0 + (size_t)kNQ*kD;
__host__ __device__ constexpr size_t O_TA2 = O_TA1 + (size_t)kNS*kD;
__host__ __device__ constexpr size_t O_TB0 = O_TA2 + (size_t)kNQ*kD;   // reused: QTT
__host__ __device__ constexpr size_t O_TB1 = O_TB0 + (size_t)kNQ*kD;
__host__ __device__ constexpr size_t O_A   = O_TB1 + (size_t)kNS*kD;
__host__ __device__ constexpr size_t O_H   = O_A   + (size_t)kNQ*kD;  // Ht: [b][d][s]
__host__ __device__ constexpr size_t O_AS  = O_H   + (size_t)kB*kS*kD;
__host__ __device__ constexpr size_t O_V   = O_AS  + (size_t)kB*kT;   // qv[128], kv[128], c_q, c_k
__host__ __device__ constexpr size_t O_RG  = O_V   + 258;             // r_gates 2x512
__host__ __device__ constexpr size_t G_TOTAL = O_RG + 1024;

__device__ float g_buf[G_TOTAL];

// ---------------- fast math ----------------
__device__ __forceinline__ float fast_tanh(float x) {
    float y;
    asm("tanh.approx.f32 %0, %1;" : "=f"(y) : "f"(x));
    return y;
}
__device__ __forceinline__ float fast_sigmoid(float x) {
    return 0.5f * fast_tanh(0.5f * x) + 0.5f;
}

// ---------------- task structs ----------------
struct GemmTask {
    const float* base;
    const int*   rowmap;   // optional indirection for base rows
    const int*   nbrs;
    const float* tbl;
    const float* W;        // [128 x ldw] slice, 128 cols used
    const float* bias;     // used if act != 2
    float*       out;
    int knbr; float invk;
    int ldw, ldo, act;     // act: 0 tanh, 1 relu, 2 none
    int R; int blk0;
};
struct PrepArgs {
    const float *qW, *qb, *kW, *kb, *wW, *embr, *Wih, *bih, *bhh;
    int enable;
};
struct GemmParams { GemmTask t[3]; int nt; PrepArgs prep; };

// ---------------- unified GEMM kernel: 128 thr, 64 rows x 128 cols, 8x8 tiles ----------------
// smem: sW[k][128] 64KB + sT[k][68] (input transposed, k-major) 34.8KB -> 2 blocks/SM.
#define ST_LD 68
__global__ __launch_bounds__(128, 2) void gemm_kernel(const GemmParams p)
{
    extern __shared__ float sm[];
    float* sW = sm;             // 128*128
    float* sT = sm + kD*kD;     // 128*68, [k][row]
    const int tid = threadIdx.x;

    // prep block (independent side-work; consumers run kernels later)
    if (p.prep.enable && blockIdx.x == (int)gridDim.x - 1) {
        const PrepArgs& A = p.prep;
        float* vec = g_buf + O_V;
        float* rg  = g_buf + O_RG;
        if (tid < kD) {
            float sq = 0.f, sk = 0.f;
            #pragma unroll 4
            for (int j = 0; j < kD; j++) {
                sq += A.qW[tid*kD + j] * A.wW[j];
                sk += A.kW[tid*kD + j] * A.wW[kD + j];
            }
            vec[tid]      = sq;
            vec[kD + tid] = sk;
        }
        if (tid == 0) {
            float s = 0.f;
            for (int j = 0; j < kD; j++) s += A.qb[j] * A.wW[j];
            vec[256] = s;
        }
        if (tid == 1) {
            float s = 0.f;
            for (int j = 0; j < kD; j++) s += A.kb[j] * A.wW[kD + j];
            vec[257] = s;
        }
        for (int c = tid; c < 512; c += 128) {
            for (int r = 0; r < 2; r++) {
                float s = A.bih[c] + A.bhh[c];
                #pragma unroll 4
                for (int k = 0; k < kD; k++)
                    s += A.embr[r*kD + k] * A.Wih[(size_t)(kD + k)*512 + c];
                rg[r*512 + c] = s;
            }
        }
        return;
    }

    int ti = 0;
    #pragma unroll
    for (int i = 1; i < 3; i++)
        if (i < p.nt && (int)blockIdx.x >= p.t[i].blk0) ti = i;
    const GemmTask& T = p.t[ti];
    const int row0 = (blockIdx.x - T.blk0) * 64;

    // load W: 4096 float4 / 128 thr = 32 each
    {
        #pragma unroll
        for (int i = 0; i < 32; i++) {
            int idx = tid + i*128;
            int k = idx >> 5, c4 = idx & 31;
            *(float4*)(sW + k*kD + c4*4) =
                __ldg((const float4*)(T.W + (size_t)k*T.ldw) + c4);
        }
    }

    // gather 64 rows: 2 thr/row, each handles 64 dims (16 float4); store TRANSPOSED
    {
        int lr = tid >> 1, part = tid & 1;
        int gr = row0 + lr;
        float4 v[16];
        if (gr < T.R) {
            int src = T.rowmap ? __ldg(&T.rowmap[gr]) : gr;
            const float4* bp = (const float4*)(T.base + (size_t)src*kD) + part*16;
            #pragma unroll
            for (int d = 0; d < 16; d++) v[d] = __ldg(&bp[d]);
            if (T.knbr > 0) {
                float4 s[16];
                #pragma unroll
                for (int d = 0; d < 16; d++) s[d] = make_float4(0.f,0.f,0.f,0.f);
                for (int j = 0; j < T.knbr; j++) {
                    int nb = __ldg(&T.nbrs[(size_t)gr*T.knbr + j]);
                    const float4* tp = (const float4*)(T.tbl + (size_t)nb*kD) + part*16;
                    #pragma unroll
                    for (int d = 0; d < 16; d++) {
                        float4 x = __ldg(&tp[d]);
                        s[d].x += x.x; s[d].y += x.y; s[d].z += x.z; s[d].w += x.w;
                    }
                }
                #pragma unroll
                for (int d = 0; d < 16; d++) {
                    v[d].x += s[d].x * T.invk; v[d].y += s[d].y * T.invk;
                    v[d].z += s[d].z * T.invk; v[d].w += s[d].w * T.invk;
                }
            }
        } else {
            #pragma unroll
            for (int d = 0; d < 16; d++) v[d] = make_float4(0.f,0.f,0.f,0.f);
        }
        #pragma unroll
        for (int d = 0; d < 16; d++) {
            int k0 = part*64 + d*4;
            sT[(k0+0)*ST_LD + lr] = v[d].x;
            sT[(k0+1)*ST_LD + lr] = v[d].y;
            sT[(k0+2)*ST_LD + lr] = v[d].z;
            sT[(k0+3)*ST_LD + lr] = v[d].w;
        }
    }
    __syncthreads();

    // 64x128 GEMM: thread tile 8 rows x 8 cols, all-LDS.128 operands
    const int r0 = (tid >> 4) * 8;   // 0..56
    const int c0 = (tid & 15) * 8;   // 0..120
    float acc[8][8];
    #pragma unroll
    for (int i = 0; i < 8; i++)
        #pragma unroll
        for (int j = 0; j < 8; j++) acc[i][j] = 0.f;

    #pragma unroll 4
    for (int k = 0; k < kD; k++) {
        float4 a0 = *(const float4*)(sT + k*ST_LD + r0);
        float4 a1 = *(const float4*)(sT + k*ST_LD + r0 + 4);
        float4 b0 = *(const float4*)(sW + k*kD + c0);
        float4 b1 = *(const float4*)(sW + k*kD + c0 + 4);
        float av[8] = {a0.x,a0.y,a0.z,a0.w,a1.x,a1.y,a1.z,a1.w};
        float bv[8] = {b0.x,b0.y,b0.z,b0.w,b1.x,b1.y,b1.z,b1.w};
        #pragma unroll
        for (int i = 0; i < 8; i++)
            #pragma unroll
            for (int j = 0; j < 8; j++)
                acc[i][j] += av[i]*bv[j];
    }

    float bsv[8];
    #pragma unroll
    for (int j = 0; j < 8; j++) bsv[j] = (T.act != 2) ? __ldg(&T.bias[c0 + j]) : 0.f;

    #pragma unroll
    for (int i = 0; i < 8; i++) {
        int gr = row0 + r0 + i;
        if (gr >= T.R) continue;
        float o[8];
        #pragma unroll
        for (int j = 0; j < 8; j++) {
            float v = acc[i][j] + bsv[j];
            if (T.act == 0)      v = fast_tanh(v);
            else if (T.act == 1) v = fmaxf(v, 0.f);
            o[j] = v;
        }
        *(float4*)(T.out + (size_t)gr*T.ldo + c0)     = make_float4(o[0],o[1],o[2],o[3]);
        *(float4*)(T.out + (size_t)gr*T.ldo + c0 + 4) = make_float4(o[4],o[5],o[6],o[7]);
    }
}

// ---------------- combine: G (i|g|o raw) + RG -> h -> Ht transposed + AS ----------------
__global__ __launch_bounds__(256, 4) void combine_kernel(const int* __restrict__ response)
{
    const float* G   = g_buf + O_TA0;   // [6400][384]
    const float* RG  = g_buf + O_RG;
    const float* vec = g_buf + O_V;
    float* Ht = g_buf + O_H;
    float* AS = g_buf + O_AS;

    const int tid = threadIdx.x;
    const int row = blockIdx.x * 16 + (tid >> 4);
    const int d0  = (tid & 15) * 8;
    const int rr  = __ldg(&response[row]);
    const int b = row / kS, s = row % kS;
    const float* gp = G + (size_t)row*384;

    float hv[8];
    float pacc = 0.f;
    #pragma unroll
    for (int jj = 0; jj < 2; jj++) {
        float4 gi = *(const float4*)(gp + d0 + jj*4);
        float4 gg = *(const float4*)(gp + 128 + d0 + jj*4);
        float4 go = *(const float4*)(gp + 256 + d0 + jj*4);
        float iv4[4] = {gi.x,gi.y,gi.z,gi.w};
        float gv4[4] = {gg.x,gg.y,gg.z,gg.w};
        float ov4[4] = {go.x,go.y,go.z,go.w};
        #pragma unroll
        for (int e = 0; e < 4; e++) {
            int j = jj*4 + e;
            float iv = fast_sigmoid(iv4[e] + RG[rr*512 + d0 + j]);
            float gv = fast_tanh   (gv4[e] + RG[rr*512 + 256 + d0 + j]);
            float ov = fast_sigmoid(ov4[e] + RG[rr*512 + 384 + d0 + j]);
            hv[j] = ov * fast_tanh(iv * gv);
            pacc += hv[j] * vec[d0 + j];
        }
    }
    #pragma unroll
    for (int j = 0; j < 8; j++)
        Ht[((size_t)b*kD + d0 + j)*kS + s] = hv[j];

    pacc += __shfl_down_sync(0xffffffffu, pacc, 8, 16);
    pacc += __shfl_down_sync(0xffffffffu, pacc, 4, 16);
    pacc += __shfl_down_sync(0xffffffffu, pacc, 2, 16);
    pacc += __shfl_down_sync(0xffffffffu, pacc, 1, 16);
    if ((tid & 15) == 0 && s < kT)
        AS[b*kT + s] = pacc + vec[256];
}

// ---------------- pred: one warp per (b,t); lane owns 4 consecutive n; exact-quad striding ----------------
__global__ __launch_bounds__(32, 24) void pred_kernel(
    const int* __restrict__ question,
    const int* __restrict__ qs_skills,
    const float* __restrict__ emb_q,
    const float* __restrict__ emb_s,
    float* __restrict__ out)
{
    const float* Ht  = g_buf + O_H;
    const float* as  = g_buf + O_AS;
    const float* vec = g_buf + O_V;

    __shared__ __align__(16) float sqs[5][kD];

    const int t = kT - 1 - blockIdx.x;     // big t first
    const int b = blockIdx.y;
    const int lane = threadIdx.x;

    int q = __ldg(&question[b*kS + t + 1]);
    ((float4*)sqs[0])[lane] = __ldg((const float4*)(emb_q + (size_t)q*kD) + lane);
    #pragma unroll
    for (int m = 1; m < 5; m++) {
        int si = __ldg(&qs_skills[q*4 + m - 1]);
        ((float4*)sqs[m])[lane] = __ldg((const float4*)(emb_s + (size_t)si*kD) + lane);
    }
    __syncwarp();

    // a_qs softmax over m (c_k cancels)
    float4 kv4 = *((const float4*)(vec + kD) + lane);
    float r[5];
    #pragma unroll
    for (int m = 0; m < 5; m++) {
        float4 s4 = ((float4*)sqs[m])[lane];
        float p = s4.x*kv4.x + s4.y*kv4.y + s4.z*kv4.z + s4.w*kv4.w;
        #pragma unroll
        for (int o = 16; o; o >>= 1) p += __shfl_xor_sync(0xffffffffu, p, o);
        r[m] = p;
    }
    {
        float mx = r[0];
        #pragma unroll
        for (int m = 1; m < 5; m++) mx = fmaxf(mx, r[m]);
        float se = 0.f;
        #pragma unroll
        for (int m = 0; m < 5; m++) { r[m] = __expf(r[m] - mx); se += r[m]; }
        float inv = __frcp_rn(se);
        #pragma unroll
        for (int m = 0; m < 5; m++) r[m] *= inv;
    }

    const float* asb = as + b*kT;

    float M1 = -1e30f;
    for (int n = lane; n <= t; n += 32) M1 = fmaxf(M1, asb[n]);
    #pragma unroll
    for (int o = 16; o; o >>= 1) M1 = fmaxf(M1, __shfl_xor_sync(0xffffffffu, M1, o));

    const float* hb = Ht + (size_t)b*kD*kS;
    float sum_v = 0.f, sum_e = 0.f;

    const int nquads = (t >> 2) + 1;       // quads covering n = 0..t
    for (int qi = lane; qi < nquads; qi += 32) {
        const int n0 = qi * 4;
        const float* hcol = hb + n0;
        float a0[4] = {0.f,0.f,0.f,0.f};
        float a1[4] = {0.f,0.f,0.f,0.f};
        float a2[4] = {0.f,0.f,0.f,0.f};
        float a3[4] = {0.f,0.f,0.f,0.f};
        float a4[4] = {0.f,0.f,0.f,0.f};

        #pragma unroll 2
        for (int d = 0; d < kD; d += 4) {
            float4 s0 = *(const float4*)&sqs[0][d];
            float4 s1 = *(const float4*)&sqs[1][d];
            float4 s2 = *(const float4*)&sqs[2][d];
            float4 s3 = *(const float4*)&sqs[3][d];
            float4 s4 = *(const float4*)&sqs[4][d];
            #pragma unroll
            for (int dd = 0; dd < 4; dd++) {
                float4 hv = *(const float4*)(hcol + (size_t)(d + dd)*kS);
                float c0v = (&s0.x)[dd];
                float c1v = (&s1.x)[dd];
                float c2v = (&s2.x)[dd];
                float c3v = (&s3.x)[dd];
                float c4v = (&s4.x)[dd];
                a0[0] += hv.x*c0v; a0[1] += hv.y*c0v; a0[2] += hv.z*c0v; a0[3] += hv.w*c0v;
                a1[0] += hv.x*c1v; a1[1] += hv.y*c1v; a1[2] += hv.z*c1v; a1[3] += hv.w*c1v;
                a2[0] += hv.x*c2v; a2[1] += hv.y*c2v; a2[2] += hv.z*c2v; a2[3] += hv.w*c2v;
                a3[0] += hv.x*c3v; a3[1] += hv.y*c3v; a3[2] += hv.z*c3v; a3[3] += hv.w*c3v;
                a4[0] += hv.x*c4v; a4[1] += hv.y*c4v; a4[2] += hv.z*c4v; a4[3] += hv.w*c4v;
            }
        }

        #pragma unroll
        for (int j = 0; j < 4; j++) {
            int n = n0 + j;
            if (n <= t) {
                float e = __expf(asb[n] - M1);
                float sv = r[0]*fast_sigmoid(a0[j]) + r[1]*fast_sigmoid(a1[j])
                         + r[2]*fast_sigmoid(a2[j]) + r[3]*fast_sigmoid(a3[j])
                         + r[4]*fast_sigmoid(a4[j]);
                sum_v += e * sv;
                sum_e += e;
            }
        }
    }
    #pragma unroll
    for (int o = 16; o; o >>= 1) {
        sum_v += __shfl_xor_sync(0xffffffffu, sum_v, o);
        sum_e += __shfl_xor_sync(0xffffffffu, sum_e, o);
    }
    if (lane == 0) {
        out[b*kS + t + 1] = sum_v / sum_e;
        if (t == 0) out[b*kS] = 0.f;
    }
}

// ---------------- launch ----------------
extern "C" void kernel_launch(void* const* d_in, const int* in_sizes, int n_in,
                              void* d_out, int out_size)
{
    const int*   question = (const int*)  d_in[0];
    const int*   response = (const int*)  d_in[1];
    const int*   q_nbr    = (const int*)  d_in[3];
    const int*   s_nbr    = (const int*)  d_in[4];
    const int*   qs_sk    = (const int*)  d_in[5];
    const float* emb_q    = (const float*)d_in[6];
    const float* emb_s    = (const float*)d_in[7];
    const float* emb_r    = (const float*)d_in[8];
    const float* W_ih     = (const float*)d_in[9];
    const float* b_ih     = (const float*)d_in[10];
    const float* b_hh     = (const float*)d_in[11];
    const float* ft_W     = (const float*)d_in[12];
    const float* ft_b     = (const float*)d_in[13];
    const float* agg_W    = (const float*)d_in[14];
    const float* agg_b    = (const float*)d_in[15];
    const float* last_W   = (const float*)d_in[16];
    const float* last_b   = (const float*)d_in[17];
    const float* q_W      = (const float*)d_in[18];
    const float* q_b      = (const float*)d_in[19];
    const float* k_W      = (const float*)d_in[20];
    const float* k_b      = (const float*)d_in[21];
    const float* w_W      = (const float*)d_in[22];
    float* out = (float*)d_out;

    float* buf = nullptr;
    cudaGetSymbolAddress((void**)&buf, g_buf);
    float* TA0 = buf + O_TA0;
    float* TA1 = buf + O_TA1;
    float* TA2 = buf + O_TA2;
    float* TB0 = buf + O_TB0;
    float* TB1 = buf + O_TB1;
    float* TC0 = buf + O_TA0;   // reuse: TA0 dead after level 1
    float* A   = buf + O_A;
    float* QTT = buf + O_TB0;   // reuse: TB0 dead after level 2
    float* G   = buf + O_TA0;   // reuse: TC0 dead after last; 6400*384 fits before O_TB0

    const int GEMM_SMEM = (kD*kD + kD*ST_LD) * (int)sizeof(float);  // ~100 KB
    static bool attr_done = false;
    if (!attr_done) {
        cudaFuncSetAttribute(gemm_kernel, cudaFuncAttributeMaxDynamicSharedMemorySize, GEMM_SMEM);
        attr_done = true;
    }

    const int gq = (kNQ + 63) / 64;    // 157
    const int gs = (kNS + 63) / 64;    // 8
    const int gr = (kB*kS) / 64;       // 100
    const float iq = 1.f/kQN, is = 1.f/kSN;

    PrepArgs noprep = {}; noprep.enable = 0;

    // level 0: TA0, TA2, TA1 (+prep)
    {
        GemmParams p;
        p.nt = 3;
        p.t[0] = { emb_q, nullptr, q_nbr, emb_s, agg_W,           agg_b,       TA0, kQN, iq, kD, kD, 0, kNQ, 0 };
        p.t[1] = { emb_q, nullptr, q_nbr, emb_s, agg_W + 2*16384, agg_b + 256, TA2, kQN, iq, kD, kD, 0, kNQ, gq };
        p.t[2] = { emb_s, nullptr, s_nbr, emb_q, agg_W + 16384,   agg_b + 128, TA1, kSN, is, kD, kD, 0, kNS, 2*gq };
        p.prep = { q_W, q_b, k_W, k_b, w_W, emb_r, W_ih, b_ih, b_hh, 1 };
        gemm_kernel<<<2*gq + gs + 1, 128, GEMM_SMEM>>>(p);
    }
    // level 1: TB0, TB1
    {
        GemmParams p;
        p.nt = 2;
        p.t[0] = { TA0, nullptr, q_nbr, TA1, agg_W,         agg_b,       TB0, kQN, iq, kD, kD, 0, kNQ, 0 };
        p.t[1] = { TA1, nullptr, s_nbr, TA2, agg_W + 16384, agg_b + 128, TB1, kSN, is, kD, kD, 0, kNS, gq };
        p.t[2] = p.t[1];
        p.prep = noprep;
        gemm_kernel<<<gq + gs, 128, GEMM_SMEM>>>(p);
    }
    // level 2: TC0
    {
        GemmParams p;
        p.nt = 1;
        p.t[0] = { TB0, nullptr, q_nbr, TB1, agg_W, agg_b, TC0, kQN, iq, kD, kD, 0, kNQ, 0 };
        p.t[1] = p.t[0]; p.t[2] = p.t[0];
        p.prep = noprep;
        gemm_kernel<<<gq, 128, GEMM_SMEM>>>(p);
    }
    // last projection: A
    {
        GemmParams p;
        p.nt = 1;
        p.t[0] = { TC0, nullptr, nullptr, nullptr, last_W, last_b, A, 0, 0.f, kD, kD, 0, kNQ, 0 };
        p.t[1] = p.t[0]; p.t[2] = p.t[0];
        p.prep = noprep;
        gemm_kernel<<<gq, 128, GEMM_SMEM>>>(p);
    }
    // QT table over all questions: QTT = relu(A @ ft_W + ft_b)
    {
        GemmParams p;
        p.nt = 1;
        p.t[0] = { A, nullptr, nullptr, nullptr, ft_W, ft_b, QTT, 0, 0.f, kD, kD, 1, kNQ, 0 };
        p.t[1] = p.t[0]; p.t[2] = p.t[0];
        p.prep = noprep;
        gemm_kernel<<<gq, 128, GEMM_SMEM>>>(p);
    }
    // gates: G[row] = QTT[question[row]] @ W_ih[:, {i,g,o}] (raw, RG added in combine)
    {
        GemmParams p;
        p.nt = 3;
        p.t[0] = { QTT, question, nullptr, nullptr, W_ih,       nullptr, G,       0, 0.f, 512, 384, 2, kB*kS, 0 };
        p.t[1] = { QTT, question, nullptr, nullptr, W_ih + 256, nullptr, G + 128, 0, 0.f, 512, 384, 2, kB*kS, gr };
        p.t[2] = { QTT, question, nullptr, nullptr, W_ih + 384, nullptr, G + 256, 0, 0.f, 512, 384, 2, kB*kS, 2*gr };
        p.prep = noprep;
        gemm_kernel<<<3*gr, 128, GEMM_SMEM>>>(p);
    }

    combine_kernel<<<(kB*kS)/16, 256>>>(response);

    dim3 pg(kT, kB);
    pred_kernel<<<pg, 32>>>(question, qs_sk, emb_q, emb_s, out);
}